// round 17
// baseline (speedup 1.0000x reference)
#include <cuda_runtime.h>
#include <cuda_fp16.h>
#include <cstdint>

#define D_MODEL 1024
#define N_EXP   8
#define N_TOK   8192
#define CAP     8192
#define MB_MAX  64
#define BM      128
#define BN      128
#define KTILES  32
#define NTHREADS 128
#define STAGE_B 16384         // 8KB A + 8KB B per stage
#define NSTAGE  4
#define SMEM_T  (NSTAGE * STAGE_B) // 64 KB
#define NWBLK   4096          // w_perm blocks in merged prep launch
#define NA1BLK  16384         // a1_perm blocks

// ---------------- device scratch ----------------
__device__ int    g_cnt[N_EXP];
__device__ int    g_tok[N_EXP * CAP];
__device__ float  g_wgt[N_EXP * CAP];
__device__ int    g_g1done[N_EXP * MB_MAX];
// fragment-permuted fp16 tiles: [e][mb][kt][4096 halves]
__device__ __half g_A1h[(size_t)N_EXP * MB_MAX * KTILES * 4096];
__device__ __half g_A2h[(size_t)N_EXP * MB_MAX * KTILES * 4096];
// fragment-permuted fp16 weights: [e][nb(8)][kt][4096 halves]
__device__ __half g_W1h[(size_t)N_EXP * 8 * KTILES * 4096];
__device__ __half g_W2h[(size_t)N_EXP * 8 * KTILES * 4096];

// ---------------- helpers ----------------
__device__ __forceinline__ uint32_t smem_u32(const void* p) {
    uint32_t a;
    asm("{ .reg .u64 t; cvta.to.shared.u64 t, %1; cvt.u32.u64 %0, t; }" : "=r"(a) : "l"(p));
    return a;
}
__device__ __forceinline__ void mma_f16(float* c, const uint32_t* a, const uint32_t* b) {
    asm volatile(
        "mma.sync.aligned.m16n8k16.row.col.f32.f16.f16.f32 "
        "{%0,%1,%2,%3}, {%4,%5,%6,%7}, {%8,%9}, {%0,%1,%2,%3};"
        : "+f"(c[0]), "+f"(c[1]), "+f"(c[2]), "+f"(c[3])
        : "r"(a[0]), "r"(a[1]), "r"(a[2]), "r"(a[3]),
          "r"(b[0]), "r"(b[1]));
}
#define CP_ASYNC16(dst, src) \
    asm volatile("cp.async.cg.shared.global [%0], [%1], 16;" :: "r"(dst), "l"(src))
#define CP_COMMIT()  asm volatile("cp.async.commit_group;" ::: "memory")
#define CP_WAIT2()   asm volatile("cp.async.wait_group 2;" ::: "memory")
#define CP_WAIT0()   asm volatile("cp.async.wait_group 0;" ::: "memory")
#define LDS128(r, a) \
    asm volatile("ld.shared.v4.b32 {%0,%1,%2,%3}, [%4];" \
        : "=r"((r)[0]), "=r"((r)[1]), "=r"((r)[2]), "=r"((r)[3]) : "r"(a))
#define LDS64(r, a) \
    asm volatile("ld.shared.v2.b32 {%0,%1}, [%2];" \
        : "=r"((r)[0]), "=r"((r)[1]) : "r"(a))

// fp16 m16n8k16 fragment slots (indices in halves), r in 0..127, k in 0..31
__device__ __forceinline__ int a_fidx16(int r, int k) {
    return (((r >> 4) * 2 + (k >> 4)) << 8) +
           (((r & 7) * 4 + ((k >> 1) & 3)) << 3) +
           ((((r >> 3) & 1) + 2 * ((k >> 3) & 1)) << 1) + (k & 1);
}
__device__ __forceinline__ int b_fidx16(int n, int k) {
    return (((n >> 3) * 2 + (k >> 4)) << 7) +
           (((n & 7) * 4 + ((k >> 1) & 3)) << 2) +
           (((k >> 3) & 1) << 1) + (k & 1);
}

// ---------------- kernel: reset counters/flags ----------------
__global__ void zero_cnt_kernel() {
    int t = threadIdx.x;
    if (t < N_EXP) g_cnt[t] = 0;
    for (int i = t; i < N_EXP * MB_MAX; i += 256) g_g1done[i] = 0;
}

// ---------------- kernel: gating + top-2 ----------------
__global__ void gate_kernel(const float* __restrict__ x,
                            const float* __restrict__ Wg,
                            const float* __restrict__ bg) {
    int tok  = blockIdx.x * 8 + (threadIdx.x >> 5);
    int lane = threadIdx.x & 31;
    if (tok >= N_TOK) return;
    const float* xr = x + (size_t)tok * D_MODEL;

    float s[8];
#pragma unroll
    for (int e = 0; e < 8; e++) s[e] = 0.f;
    for (int k = lane; k < D_MODEL; k += 32) {
        float xv = xr[k];
        const float4* wr = (const float4*)(Wg + (size_t)k * N_EXP);
        float4 w0 = wr[0], w1 = wr[1];
        s[0] += xv * w0.x; s[1] += xv * w0.y; s[2] += xv * w0.z; s[3] += xv * w0.w;
        s[4] += xv * w1.x; s[5] += xv * w1.y; s[6] += xv * w1.z; s[7] += xv * w1.w;
    }
#pragma unroll
    for (int e = 0; e < 8; e++)
#pragma unroll
        for (int off = 16; off > 0; off >>= 1)
            s[e] += __shfl_xor_sync(0xffffffffu, s[e], off);

    if (lane == 0) {
        float best = -3.4e38f, best2 = -3.4e38f;
        int e0 = 0, e1 = 0;
#pragma unroll
        for (int e = 0; e < 8; e++) {
            float v = s[e] + bg[e];
            if (v > best)       { best2 = best; e1 = e0; best = v; e0 = e; }
            else if (v > best2) { best2 = v; e1 = e; }
        }
        int p0 = atomicAdd(&g_cnt[e0], 1);
        g_tok[e0 * CAP + p0] = tok;
        g_wgt[e0 * CAP + p0] = best;
        int p1 = atomicAdd(&g_cnt[e1], 1);
        g_tok[e1 * CAP + p1] = tok;
        g_wgt[e1 * CAP + p1] = best2;
    }
}

// ---------------- kernel: merged prep (w_perm + a1_perm), 1D grid ----------
__global__ void prep_kernel(const float* __restrict__ W1,
                            const float* __restrict__ W2,
                            const float* __restrict__ x) {
    __shared__ __half stg[4096];
    const int bid = blockIdx.x;
    const int tid = threadIdx.x;

    if (bid < NWBLK) {
        // ---- weight permute: decode (kt, nb, which, e) ----
        const int kt = bid & 31;
        const int nb = (bid >> 5) & 7;
        const int ez = bid >> 8;
        const int which = ez >> 3;
        const int e     = ez & 7;
        const float* W  = which ? W2 : W1;
        __half* dst     = which ? g_W2h : g_W1h;
        const int kp  = tid >> 4;          // k-pair 0..15
        const int nc  = tid & 15;          // column group (8 n each)
        const float* Ws = W + (size_t)e * D_MODEL * D_MODEL;
        __half2* stg2 = (__half2*)stg;
#pragma unroll
        for (int i = 0; i < 2; i++) {
            int n_in = nc * 8 + i * 4;
            const float* r0 = Ws + (size_t)(kt * 32 + 2 * kp) * D_MODEL + nb * 128 + n_in;
            float4 v0 = *(const float4*)r0;
            float4 v1 = *(const float4*)(r0 + D_MODEL);
            stg2[b_fidx16(n_in + 0, 2 * kp) >> 1] = __floats2half2_rn(v0.x, v1.x);
            stg2[b_fidx16(n_in + 1, 2 * kp) >> 1] = __floats2half2_rn(v0.y, v1.y);
            stg2[b_fidx16(n_in + 2, 2 * kp) >> 1] = __floats2half2_rn(v0.z, v1.z);
            stg2[b_fidx16(n_in + 3, 2 * kp) >> 1] = __floats2half2_rn(v0.w, v1.w);
        }
        __syncthreads();
        uint4* d4 = (uint4*)(dst + ((size_t)(e * 8 + nb) * KTILES + kt) * 4096);
        const uint4* s4 = (const uint4*)stg;
        d4[tid]       = s4[tid];
        d4[tid + 256] = s4[tid + 256];
    } else {
        // ---- A1 gather+permute: decode (mb, e, kt) ----
        const int t  = bid - NWBLK;
        const int mb = t & 63;
        const int e  = (t >> 6) & 7;
        const int kt = t >> 9;
        const int cnt = g_cnt[e];
        if (mb * BM >= cnt) return;
        const int r   = tid >> 1;
        const int hlf = tid & 1;
        int ai  = mb * BM + r;
        int tok = (ai < cnt) ? g_tok[e * CAP + ai] : g_tok[e * CAP];
        const float* src = x + (size_t)tok * D_MODEL + kt * 32 + hlf * 16;
#pragma unroll
        for (int i = 0; i < 4; i++) {
            int k_in = hlf * 16 + i * 4;
            float4 v = *(const float4*)(src + i * 4);
            stg[a_fidx16(r, k_in + 0)] = __float2half_rn(v.x);
            stg[a_fidx16(r, k_in + 1)] = __float2half_rn(v.y);
            stg[a_fidx16(r, k_in + 2)] = __float2half_rn(v.z);
            stg[a_fidx16(r, k_in + 3)] = __float2half_rn(v.w);
        }
        __syncthreads();
        uint4* d4 = (uint4*)(g_A1h + ((size_t)(e * MB_MAX + mb) * KTILES + kt) * 4096);
        const uint4* s4 = (const uint4*)stg;
        d4[tid]       = s4[tid];
        d4[tid + 256] = s4[tid + 256];
    }
}

// ---------------- kernel: merged grouped GEMM1+GEMM2 ----------------
// grid (8, 64, 16): z<8 -> GEMM1 expert z ; z>=8 -> GEMM2 expert z-8.
// FIFO dispatch (z slowest) => all GEMM1 CTAs dispatched before any GEMM2 CTA,
// so the per-(e,mb) flag spin cannot deadlock.
__global__ void __launch_bounds__(NTHREADS, 2)
moe_gemm(const float* __restrict__ b1, const float* __restrict__ b2,
         float* __restrict__ out) {
    const bool FIRST = blockIdx.z < 8;
    const int e   = blockIdx.z & 7;
    const int cnt = g_cnt[e];
    const int mb  = blockIdx.y;
    if (mb * BM >= cnt) return;
    const int nb  = blockIdx.x;
    const int em  = e * MB_MAX + mb;

    extern __shared__ __align__(128) char smem[];
    const uint32_t sb = smem_u32(smem);
    const int tid  = threadIdx.x;
    const int lane = tid & 31;
    const int warp = tid >> 5;
    const int wm   = warp >> 1;          // 0..1 (64-row)
    const int wn   = warp & 1;           // 0..1 (64-col)
    const int g    = lane >> 2;
    const int tg   = lane & 3;

    if (!FIRST) {
        if (tid == 0) {
            volatile int* f = &g_g1done[em];
            while (*f < 8) __nanosleep(64);
        }
        __syncthreads();
    }

    const __half* Asrc = (FIRST ? g_A1h : g_A2h) + (size_t)em * KTILES * 4096;
    const __half* Bsrc = (FIRST ? g_W1h : g_W2h) + (size_t)(e * 8 + nb) * KTILES * 4096;

    float c[32][4];
#pragma unroll
    for (int i = 0; i < 32; i++)
#pragma unroll
        for (int j = 0; j < 4; j++) c[i][j] = 0.f;

    // stage layout: [0,8K) A | [8K,16K) B
    auto load_stage = [&](int kt, int s) {
        uint32_t da = sb + s * STAGE_B + tid * 16;
        const char* sa = (const char*)(Asrc + (size_t)kt * 4096) + tid * 16;
        const char* sw = (const char*)(Bsrc + (size_t)kt * 4096) + tid * 16;
#pragma unroll
        for (int cc = 0; cc < 4; cc++) {
            CP_ASYNC16(da + cc * 2048,        sa + cc * 2048);
            CP_ASYNC16(da + 8192 + cc * 2048, sw + cc * 2048);
        }
    };

    load_stage(0, 0); CP_COMMIT();
    load_stage(1, 1); CP_COMMIT();
    load_stage(2, 2); CP_COMMIT();

    const uint32_t aoff = wm * 4096 + lane * 16;          // A frag base (bytes)
    const uint32_t boff = 8192 + wn * 4096 + lane * 8;    // B frag base (bytes)

    for (int it = 0; it < KTILES; it++) {
        CP_WAIT2();
        __syncthreads();
        if (it + 3 < KTILES) load_stage(it + 3, (it + 3) & 3);
        CP_COMMIT();

        const uint32_t st = sb + (it & 3) * STAGE_B;
#pragma unroll
        for (int kk = 0; kk < 2; kk++) {
            uint32_t a[4][4], b[8][2];
#pragma unroll
            for (int mi = 0; mi < 4; mi++)
                LDS128(a[mi], st + aoff + mi * 1024 + kk * 512);
#pragma unroll
            for (int ni = 0; ni < 8; ni++)
                LDS64(b[ni], st + boff + ni * 512 + kk * 256);
#pragma unroll
            for (int mi = 0; mi < 4; mi++)
#pragma unroll
                for (int ni = 0; ni < 8; ni++)
                    mma_f16(c[mi * 8 + ni], a[mi], b[ni]);
        }
    }

    // ---- epilogue ----
    if (FIRST) {
        const float* brow = b1 + e * D_MODEL;
        // stage permuted relu(bias+acc) tile in smem, then coalesced copy-out
        CP_WAIT0();
        __syncthreads();
        __half2* ep2 = (__half2*)smem;
#pragma unroll
        for (int mi = 0; mi < 4; mi++) {
#pragma unroll
            for (int ni = 0; ni < 8; ni++) {
#pragma unroll
                for (int jp = 0; jp < 2; jp++) {
                    int r_blk = wm * 64 + mi * 16 + g + 8 * jp;
                    int n0    = wn * 64 + ni * 8 + 2 * tg;     // even, 0..126
                    int n_glob = nb * BN + n0;
                    float v0 = fmaxf(c[mi * 8 + ni][jp * 2 + 0] + __ldg(brow + n_glob), 0.f);
                    float v1 = fmaxf(c[mi * 8 + ni][jp * 2 + 1] + __ldg(brow + n_glob + 1), 0.f);
                    int idx = (n0 >> 5) * 4096 + a_fidx16(r_blk, n0 & 31);  // even
                    ep2[idx >> 1] = __floats2half2_rn(v0, v1);
                }
            }
        }
        __syncthreads();
        uint4* d4 = (uint4*)(g_A2h + ((size_t)em * KTILES + nb * 4) * 4096);
        const uint4* s4 = (const uint4*)smem;
#pragma unroll
        for (int i = 0; i < 16; i++)
            d4[tid + i * 128] = s4[tid + i * 128];
        __threadfence();
        __syncthreads();
        if (tid == 0) atomicAdd(&g_g1done[em], 1);
    } else {
        const float* brow = b2 + e * D_MODEL;
#pragma unroll
        for (int mi = 0; mi < 4; mi++) {
#pragma unroll
            for (int ni = 0; ni < 8; ni++) {
#pragma unroll
                for (int j = 0; j < 4; j++) {
                    int r_blk = wm * 64 + mi * 16 + g + 8 * (j >> 1);
                    int grow  = mb * BM + r_blk;
                    if (grow >= cnt) continue;
                    int n_glob = nb * BN + wn * 64 + ni * 8 + 2 * tg + (j & 1);
                    float v = c[mi * 8 + ni][j] + __ldg(brow + n_glob);
                    float w = g_wgt[e * CAP + grow];
                    atomicAdd(out + (size_t)g_tok[e * CAP + grow] * D_MODEL + n_glob,
                              v * w);
                }
            }
        }
    }
}

// ---------------- launch ----------------
extern "C" void kernel_launch(void* const* d_in, const int* in_sizes, int n_in,
                              void* d_out, int out_size) {
    const float* x  = (const float*)d_in[0];
    const float* Wg = (const float*)d_in[1];
    const float* bg = (const float*)d_in[2];
    const float* W1 = (const float*)d_in[3];
    const float* b1 = (const float*)d_in[4];
    const float* W2 = (const float*)d_in[5];
    const float* b2 = (const float*)d_in[6];
    float* out = (float*)d_out;

    cudaFuncSetAttribute(moe_gemm,
                         cudaFuncAttributeMaxDynamicSharedMemorySize, SMEM_T);

    cudaMemsetAsync(out, 0, (size_t)out_size * sizeof(float));
    zero_cnt_kernel<<<1, 256>>>();
    gate_kernel<<<N_TOK / 8, 256>>>(x, Wg, bg);

    prep_kernel<<<NWBLK + NA1BLK, 256>>>(W1, W2, x);

    dim3 grid(D_MODEL / BN, MB_MAX, 16);   // (8, 64, 16): GEMM1 z<8, GEMM2 z>=8
    moe_gemm<<<grid, NTHREADS, SMEM_T>>>(b1, b2, out);
}